// round 1
// baseline (speedup 1.0000x reference)
#include <cuda_runtime.h>
#include <cuda_bf16.h>

// Problem constants (match reference setup_inputs)
constexpr int N_NODES = 100000;
constexpr int N_EDGES = 3200000;
constexpr int F  = 32;   // node features
constexpr int L  = 50;   // node labels
constexpr int EL = 10;   // edge labels
constexpr int K  = 16;   // out dim

// Persistent scratch (static device arrays: no runtime allocation).
// Zero-initialized at module load; kernels maintain the "zeroed" invariant
// across calls (node_update re-zeroes agg, final kernel re-zeroes sums).
__device__ float g_agg[(size_t)N_NODES * F];
__device__ float g_h  [(size_t)N_NODES * F];
__device__ float g_sums[L * F];

// ---------------------------------------------------------------------------
// Edge propagation: 8 threads per edge, each thread owns a float4 chunk.
//   msgs = W[lbl[src], lbl[dst], elabel] * x[src]  scatter-added into agg[dst]
// use_h selects input: layer 1 reads x from d_in, layers 2/3 read g_h.
// ---------------------------------------------------------------------------
__global__ __launch_bounds__(256)
void conv_edges(const float* __restrict__ x_in,
                const float* __restrict__ W,
                const int*   __restrict__ esrc,
                const int*   __restrict__ edst,
                const int*   __restrict__ elab,
                const int*   __restrict__ lbl,
                int use_h)
{
    long long t = (long long)blockIdx.x * blockDim.x + threadIdx.x;
    int e = (int)(t >> 3);
    int c = (int)(t & 7);
    if (e >= N_EDGES) return;

    const float* __restrict__ x = use_h ? g_h : x_in;

    int s  = esrc[e];
    int d  = edst[e];
    int ls = lbl[s];
    int ld = lbl[d];
    float w = W[(ls * L + ld) * EL + elab[e]];

    float4 xv = reinterpret_cast<const float4*>(x)[(size_t)s * 8 + c];
    float4 m;
    m.x = w * xv.x; m.y = w * xv.y; m.z = w * xv.z; m.w = w * xv.w;

    float* dst = &g_agg[(size_t)d * F + c * 4];
    asm volatile("red.global.add.v4.f32 [%0], {%1,%2,%3,%4};"
                 :: "l"(dst), "f"(m.x), "f"(m.y), "f"(m.z), "f"(m.w)
                 : "memory");
}

// ---------------------------------------------------------------------------
// Node update: h = tanh(agg + b[lbl]); re-zero agg for the next layer.
// ---------------------------------------------------------------------------
__global__ __launch_bounds__(256)
void node_update(const float* __restrict__ b,
                 const int*   __restrict__ lbl)
{
    int i = blockIdx.x * blockDim.x + threadIdx.x;   // over N_NODES*F
    if (i >= N_NODES * F) return;
    int n = i >> 5;                                   // F == 32
    float v = tanhf(g_agg[i] + b[lbl[n]]);
    g_h[i]   = v;
    g_agg[i] = 0.0f;
}

// ---------------------------------------------------------------------------
// Label pooling: sums[l, f] = sum over nodes with label l of h[n, f].
// Per-block SMEM accumulation, then 1600 global atomics per block.
// ---------------------------------------------------------------------------
__global__ __launch_bounds__(256)
void label_reduce(const int* __restrict__ lbl)
{
    __shared__ float s[L * F];   // 6400 floats = 25.6 KB
    for (int i = threadIdx.x; i < L * F; i += blockDim.x) s[i] = 0.0f;
    __syncthreads();

    int f          = threadIdx.x & 31;
    int nodes_per  = blockDim.x >> 5;                 // 8 nodes per iter
    int n0         = blockIdx.x * nodes_per + (threadIdx.x >> 5);
    int stride     = gridDim.x * nodes_per;

    for (int n = n0; n < N_NODES; n += stride) {
        int l = lbl[n];
        atomicAdd(&s[l * F + f], g_h[(size_t)n * F + f]);
    }
    __syncthreads();

    for (int i = threadIdx.x; i < L * F; i += blockDim.x) {
        float v = s[i];
        if (v != 0.0f) atomicAdd(&g_sums[i], v);
    }
}

// ---------------------------------------------------------------------------
// Final head: out[k] = tanh(sum_{l,f} sums[l,f] * Wr[l,f,k] + br[k]).
// Single block; zeroes g_sums afterwards to keep state invariant.
// ---------------------------------------------------------------------------
__global__ __launch_bounds__(512)
void final_head(const float* __restrict__ Wr,
                const float* __restrict__ br,
                float* __restrict__ out)
{
    __shared__ float red[512];
    int t = threadIdx.x;
    int k = t & 15;          // 16 outputs
    int chunk = t >> 4;      // 32 partial-sum chunks

    float acc = 0.0f;
    for (int i = chunk; i < L * F; i += 32)
        acc += g_sums[i] * Wr[i * K + k];
    red[t] = acc;
    __syncthreads();

    #pragma unroll
    for (int s = 256; s >= 16; s >>= 1) {
        if (t < s) red[t] += red[t + s];
        __syncthreads();
    }
    if (t < K) out[t] = tanhf(red[t] + br[t]);
    __syncthreads();

    // reset label sums for the next call
    for (int i = t; i < L * F; i += 512) g_sums[i] = 0.0f;
}

// ---------------------------------------------------------------------------
// kernel_launch
// inputs (metadata order):
// 0:x 1:W1 2:b1 3:W2 4:b2 5:W3 6:b3 7:Wr 8:br 9:node_labels
// 10:edge_src 11:edge_dst 12:edge_labels
// ---------------------------------------------------------------------------
extern "C" void kernel_launch(void* const* d_in, const int* in_sizes, int n_in,
                              void* d_out, int out_size)
{
    const float* x   = (const float*)d_in[0];
    const float* W1  = (const float*)d_in[1];
    const float* b1  = (const float*)d_in[2];
    const float* W2  = (const float*)d_in[3];
    const float* b2  = (const float*)d_in[4];
    const float* W3  = (const float*)d_in[5];
    const float* b3  = (const float*)d_in[6];
    const float* Wr  = (const float*)d_in[7];
    const float* br  = (const float*)d_in[8];
    const int* lbl   = (const int*)d_in[9];
    const int* esrc  = (const int*)d_in[10];
    const int* edst  = (const int*)d_in[11];
    const int* elab  = (const int*)d_in[12];
    float* out = (float*)d_out;

    const int edge_threads = N_EDGES * 8;
    const int eg = (edge_threads + 255) / 256;
    const int ng = (N_NODES * F + 255) / 256;

    conv_edges<<<eg, 256>>>(x, W1, esrc, edst, elab, lbl, 0);
    node_update<<<ng, 256>>>(b1, lbl);

    conv_edges<<<eg, 256>>>(x, W2, esrc, edst, elab, lbl, 1);
    node_update<<<ng, 256>>>(b2, lbl);

    conv_edges<<<eg, 256>>>(x, W3, esrc, edst, elab, lbl, 1);
    node_update<<<ng, 256>>>(b3, lbl);

    label_reduce<<<296, 256>>>(lbl);
    final_head<<<1, 512>>>(Wr, br, out);
}